// round 8
// baseline (speedup 1.0000x reference)
#include <cuda_runtime.h>
#include <math.h>

#define NB 64
#define NA 8732
#define NA4 2183            // NA/4 exact
#define NG 50
#define NC 21
#define NBX 18              // ceil(NA/512)
#define IOU_THR 0.5f
#define VXY 0.1f
#define VWH 0.2f
#define EPS16 9.765625e-4

// ---------------- device scratch ----------------
__device__ float  g_lossneg[NB * NA];
__device__ float  g_psl1[NB * NBX];
__device__ float  g_pce [NB * NBX];
__device__ int    g_pnp [NB * NBX];
__device__ double g_ob_cp[NB];
__device__ double g_ob_cn[NB];
__device__ double g_ob_np[NB];
__device__ double g_ob_sl[NB];
__device__ int    g_ctr;

// ---------------- helpers ----------------
__device__ __forceinline__ double warpRedD(double v) {
    #pragma unroll
    for (int o = 16; o > 0; o >>= 1) v += __shfl_down_sync(0xFFFFFFFFu, v, o);
    return v;
}
__device__ __forceinline__ float warpRedF(float v) {
    #pragma unroll
    for (int o = 16; o > 0; o >>= 1) v += __shfl_down_sync(0xFFFFFFFFu, v, o);
    return v;
}
__device__ __forceinline__ unsigned long long warpRedULL(unsigned long long v) {
    #pragma unroll
    for (int o = 16; o > 0; o >>= 1) v += __shfl_down_sync(0xFFFFFFFFu, v, o);
    return v;
}
__device__ __forceinline__ float smoothL1(float d) {
    float ad = fabsf(d);
    return ad < 1.0f ? 0.5f * d * d : ad - 0.5f;
}
__device__ __forceinline__ unsigned ordkey(float f) {
    unsigned u = __float_as_uint(f);
    return u ^ ((u >> 31) ? 0xFFFFFFFFu : 0x80000000u);
}
__device__ __forceinline__ float ordval(unsigned k) {
    unsigned u = (k & 0x80000000u) ? (k ^ 0x80000000u) : ~k;
    return __uint_as_float(u);
}

// ---------------- kernel 1: match + box loss + CE (2 anchors/thread) ----------------
__global__ __launch_bounds__(256) void k_match(const float* __restrict__ preg,
                        const float* __restrict__ pcls,
                        const float* __restrict__ ancs,
                        const float* __restrict__ gbox,
                        const int*   __restrict__ glab) {
    const int b = blockIdx.y;
    const int tid = threadIdx.x;
    const int a0 = blockIdx.x * 512 + tid;
    const int a1 = a0 + 256;

    __shared__ float4 s_gb[NG];
    __shared__ float  s_ga[NG];
    __shared__ int    s_gl[NG];
    if (tid < NG) {
        float4 gb = reinterpret_cast<const float4*>(gbox)[b * NG + tid];
        int    gl = glab[b * NG + tid];
        float  ag = (gb.z - gb.x) * (gb.w - gb.y);
        if (gl <= 0) { gb = make_float4(0.f, 0.f, 0.f, 0.f); ag = 0.f; }
        s_gb[tid] = gb;
        s_ga[tid] = ag;
        s_gl[tid] = gl;
    }
    __syncthreads();

    float sl1_c = 0.f, ce_c = 0.f;
    int pos_c = 0;

    const bool v0 = (a0 < NA), v1 = (a1 < NA);

    float4 anc0 = make_float4(0.5f, 0.5f, 1.f, 1.f), anc1 = anc0;
    if (v0) anc0 = reinterpret_cast<const float4*>(ancs)[a0];
    if (v1) anc1 = reinterpret_cast<const float4*>(ancs)[a1];

    float al0 = anc0.x - anc0.z * 0.5f, at0 = anc0.y - anc0.w * 0.5f;
    float ar0 = anc0.x + anc0.z * 0.5f, ab0 = anc0.y + anc0.w * 0.5f;
    float area0 = (ar0 - al0) * (ab0 - at0);
    float al1 = anc1.x - anc1.z * 0.5f, at1 = anc1.y - anc1.w * 0.5f;
    float ar1 = anc1.x + anc1.z * 0.5f, ab1 = anc1.y + anc1.w * 0.5f;
    float area1 = (ar1 - al1) * (ab1 - at1);

    float inb0 = -1.f, unb0 = 1.f, inb1 = -1.f, unb1 = 1.f;
    int bi0 = 0, bi1 = 0;
    #pragma unroll
    for (int g = 0; g < NG; g++) {
        float4 gb = s_gb[g];
        float ga = s_ga[g];
        {
            float ltx = fmaxf(gb.x, al0), lty = fmaxf(gb.y, at0);
            float rbx = fminf(gb.z, ar0), rby = fminf(gb.w, ab0);
            float w = fmaxf(rbx - ltx, 0.0f), h = fmaxf(rby - lty, 0.0f);
            float inter = w * h;
            float uni = ga + area0 - inter;
            if (inter * unb0 > inb0 * uni) { inb0 = inter; unb0 = uni; bi0 = g; }
        }
        {
            float ltx = fmaxf(gb.x, al1), lty = fmaxf(gb.y, at1);
            float rbx = fminf(gb.z, ar1), rby = fminf(gb.w, ab1);
            float w = fmaxf(rbx - ltx, 0.0f), h = fmaxf(rby - lty, 0.0f);
            float inter = w * h;
            float uni = ga + area1 - inter;
            if (inter * unb1 > inb1 * uni) { inb1 = inter; unb1 = uni; bi1 = g; }
        }
    }
    bool pos0 = (2.0f * inb0 >= unb0);
    bool pos1 = (2.0f * inb1 >= unb1);

    const float* pregb = preg + (size_t)b * 4 * NA;
    const float* pclsb = pcls + (size_t)b * NC * NA;

    if (v0) {
        float4 gb = s_gb[bi0];
        float gcx = (gb.x + gb.z) * 0.5f, gcy = (gb.y + gb.w) * 0.5f;
        float gw = gb.z - gb.x, gh = gb.w - gb.y;
        float tx = (gcx - anc0.x) / (anc0.z * VXY);
        float ty = (gcy - anc0.y) / (anc0.w * VXY);
        float tw = __logf(fmaxf(gw, 1e-6f) / anc0.z) * (1.0f / VWH);
        float th = __logf(fmaxf(gh, 1e-6f) / anc0.w) * (1.0f / VWH);
        float d0 = pregb[0 * NA + a0] - tx;
        float d1 = pregb[1 * NA + a0] - ty;
        float d2 = pregb[2 * NA + a0] - tw;
        float d3 = pregb[3 * NA + a0] - th;
        float sl1 = smoothL1(d0) + smoothL1(d1) + smoothL1(d2) + smoothL1(d3);

        const float* pc = pclsb + a0;
        float s = 0.0f;
        #pragma unroll
        for (int c = 0; c < NC; c++) s += __expf(pc[c * NA]);
        float lse = __logf(s);
        int lab = pos0 ? s_gl[bi0] : 0;
        float ce = lse - pc[lab * NA];

        g_lossneg[b * NA + a0] = pos0 ? -1.0f : ce;
        if (pos0) { pos_c++; ce_c += ce; sl1_c += sl1; }
    }
    if (v1) {
        float4 gb = s_gb[bi1];
        float gcx = (gb.x + gb.z) * 0.5f, gcy = (gb.y + gb.w) * 0.5f;
        float gw = gb.z - gb.x, gh = gb.w - gb.y;
        float tx = (gcx - anc1.x) / (anc1.z * VXY);
        float ty = (gcy - anc1.y) / (anc1.w * VXY);
        float tw = __logf(fmaxf(gw, 1e-6f) / anc1.z) * (1.0f / VWH);
        float th = __logf(fmaxf(gh, 1e-6f) / anc1.w) * (1.0f / VWH);
        float d0 = pregb[0 * NA + a1] - tx;
        float d1 = pregb[1 * NA + a1] - ty;
        float d2 = pregb[2 * NA + a1] - tw;
        float d3 = pregb[3 * NA + a1] - th;
        float sl1 = smoothL1(d0) + smoothL1(d1) + smoothL1(d2) + smoothL1(d3);

        const float* pc = pclsb + a1;
        float s = 0.0f;
        #pragma unroll
        for (int c = 0; c < NC; c++) s += __expf(pc[c * NA]);
        float lse = __logf(s);
        int lab = pos1 ? s_gl[bi1] : 0;
        float ce = lse - pc[lab * NA];

        g_lossneg[b * NA + a1] = pos1 ? -1.0f : ce;
        if (pos1) { pos_c++; ce_c += ce; sl1_c += sl1; }
    }

    sl1_c = warpRedF(sl1_c);
    ce_c  = warpRedF(ce_c);
    float posf = warpRedF((float)pos_c);
    __shared__ float sh0[8], sh1[8], sh2[8];
    int wid = tid >> 5, lid = tid & 31;
    if (lid == 0) { sh0[wid] = sl1_c; sh1[wid] = ce_c; sh2[wid] = posf; }
    __syncthreads();
    if (wid == 0) {
        float x0 = (lid < 8) ? sh0[lid] : 0.f;
        float x1 = (lid < 8) ? sh1[lid] : 0.f;
        float x2 = (lid < 8) ? sh2[lid] : 0.f;
        x0 = warpRedF(x0); x1 = warpRedF(x1); x2 = warpRedF(x2);
        if (lid == 0) {
            int p = b * NBX + blockIdx.x;
            g_psl1[p] = x0;
            g_pce [p] = x1;
            g_pnp [p] = (int)(x2 + 0.5f);
        }
    }
}

// block-wide count reduce of a packed 3x14-bit counter triple (2 barriers)
__device__ __forceinline__ unsigned long long blockRedCnt(
        unsigned long long p, unsigned long long* s_w, unsigned long long* s_tot,
        int tid, int lane, int wid) {
    p = warpRedULL(p);
    if (lane == 0) s_w[wid] = p;
    __syncthreads();
    if (wid == 0) {
        unsigned long long t = s_w[lane];
        t = warpRedULL(t);
        if (lane == 0) *s_tot = t;
    }
    __syncthreads();
    return *s_tot;
}

// ---------------- kernel 2: bisection top-K (no histograms, no smem atomics) ----------------
// Keys in registers; negatives (ce>0) have bit31 set; positives (-1.0) map to
// 0x407FFFFF; padding slots map to 0. Since K <= numneg, the K-th largest key T
// always has bit31 set, so positives/padding never enter the count or sum.
__global__ __launch_bounds__(1024) void k_select(float* __restrict__ out) {
    const int b = blockIdx.x;
    const int tid = threadIdx.x;
    const int lane = tid & 31;
    const int wid = tid >> 5;

    __shared__ unsigned long long s_w[32];
    __shared__ unsigned long long s_tot;
    __shared__ double s_np, s_ce, s_sl;
    __shared__ int s_ticket;
    __shared__ double sd[32];

    // warp 31 reduces per-block partials; others proceed to loads
    if (wid == 31) {
        double np = 0.0, ce = 0.0, sl = 0.0;
        if (lane < NBX) {
            int p = b * NBX + lane;
            np = (double)g_pnp[p];
            ce = (double)g_pce[p];
            sl = (double)g_psl1[p];
        }
        np = warpRedD(np); ce = warpRedD(ce); sl = warpRedD(sl);
        if (lane == 0) { s_np = np; s_ce = ce; s_sl = sl; }
    }

    // register-resident keys: 3 float4 per thread (12 values)
    const float4* base4 = reinterpret_cast<const float4*>(&g_lossneg[b * NA]);
    unsigned k[12];
    {
        float4 f = base4[tid];
        k[0] = ordkey(f.x); k[1] = ordkey(f.y); k[2] = ordkey(f.z); k[3] = ordkey(f.w);
        f = base4[tid + 1024];
        k[4] = ordkey(f.x); k[5] = ordkey(f.y); k[6] = ordkey(f.z); k[7] = ordkey(f.w);
        if (tid < NA4 - 2048) {
            f = base4[tid + 2048];
            k[8] = ordkey(f.x); k[9] = ordkey(f.y); k[10] = ordkey(f.z); k[11] = ordkey(f.w);
        } else {
            k[8] = k[9] = k[10] = k[11] = 0u;
        }
    }
    __syncthreads();

    int npos = (int)(s_np + 0.5);
    int numneg = NA - npos;
    int K = (npos > 0) ? min(3 * npos, numneg) : (numneg > 0 ? 1 : 0);

    double negsum = 0.0;

    if (K > 0) {
        unsigned long long Kull = (unsigned long long)K;
        unsigned T = 0x80000000u;   // bit31 of the K-th largest is always set

        // 15 rounds x 2 bits (bits 30..1), then 1 round for bit 0
        #pragma unroll
        for (int bp = 29; bp >= 1; bp -= 2) {
            unsigned c1 = T | (1u << bp);
            unsigned c2 = T | (2u << bp);
            unsigned c3 = T | (3u << bp);
            unsigned n1 = 0, n2 = 0, n3 = 0;
            #pragma unroll
            for (int j = 0; j < 12; j++) {
                n1 += (k[j] >= c1);
                n2 += (k[j] >= c2);
                n3 += (k[j] >= c3);
            }
            unsigned long long p = (unsigned long long)n1
                                 | ((unsigned long long)n2 << 14)
                                 | ((unsigned long long)n3 << 28);
            unsigned long long tot = blockRedCnt(p, s_w, &s_tot, tid, lane, wid);
            unsigned long long t1 = tot & 0x3FFFu;
            unsigned long long t2 = (tot >> 14) & 0x3FFFu;
            unsigned long long t3 = (tot >> 28) & 0x3FFFu;
            if      (t3 >= Kull) T = c3;
            else if (t2 >= Kull) T = c2;
            else if (t1 >= Kull) T = c1;
            __syncthreads();   // protect s_tot before next round overwrites
        }
        {   // bit 0
            unsigned c1 = T | 1u;
            unsigned n1 = 0;
            #pragma unroll
            for (int j = 0; j < 12; j++) n1 += (k[j] >= c1);
            unsigned long long tot = blockRedCnt((unsigned long long)n1, s_w, &s_tot, tid, lane, wid);
            if (tot >= Kull) T = c1;
            __syncthreads();
        }

        // strict count above T and sum above T
        unsigned fgt = 0;
        double sa = 0.0, sb = 0.0;
        #pragma unroll
        for (int j = 0; j < 12; j += 2) {
            if (k[j] > T)     { fgt++; sa += (double)ordval(k[j]); }
            if (k[j + 1] > T) { fgt++; sb += (double)ordval(k[j + 1]); }
        }
        unsigned long long pk = (unsigned long long)fgt;
        pk = warpRedULL(pk);
        double s = warpRedD(sa + sb);
        if (lane == 0) { s_w[wid] = pk; sd[wid] = s; }
        __syncthreads();
        if (wid == 0) {
            unsigned long long t = s_w[lane];
            double u = sd[lane];
            t = warpRedULL(t);
            u = warpRedD(u);
            if (lane == 0) {
                double r = (double)(K - (int)t);   // # of ties of value val(T) to add
                sd[0] = u + r * (double)ordval(T);
            }
        }
        __syncthreads();
        negsum = sd[0];
    }

    // publish per-batch results; last block combines
    if (tid == 0) {
        double nums = fmax(s_np, (double)EPS16);
        g_ob_cp[b] = s_ce / nums;
        g_ob_cn[b] = negsum / nums;
        g_ob_np[b] = s_np;
        g_ob_sl[b] = s_sl;
        __threadfence();
        s_ticket = atomicAdd(&g_ctr, 1);
    }
    __syncthreads();

    if (s_ticket == NB - 1) {
        double cp = 0.0, cn = 0.0, np = 0.0, sl = 0.0;
        if (tid < NB) {
            cp = g_ob_cp[tid]; cn = g_ob_cn[tid];
            np = g_ob_np[tid]; sl = g_ob_sl[tid];
        }
        cp = warpRedD(cp); cn = warpRedD(cn); np = warpRedD(np); sl = warpRedD(sl);
        __shared__ double f0[2], f1[2], f2[2], f3[2];
        if (lane == 0 && tid < NB) {
            f0[wid] = cp; f1[wid] = cn; f2[wid] = np; f3[wid] = sl;
        }
        __syncthreads();
        if (tid == 0) {
            double CP = f0[0] + f0[1];
            double CN = f1[0] + f1[1];
            double NP = f2[0] + f2[1];
            double SL = f3[0] + f3[1];
            double lbox = SL / fmax(NP, 1.0);
            out[0] = (float)(lbox + CP / (double)NB + CN / (double)NB);
            g_ctr = 0;
        }
    }
}

// ---------------- launch ----------------
extern "C" void kernel_launch(void* const* d_in, const int* in_sizes, int n_in,
                              void* d_out, int out_size) {
    const float* preg = (const float*)d_in[0];
    const float* pcls = (const float*)d_in[1];
    const float* ancs = (const float*)d_in[2];
    const float* gbox = (const float*)d_in[3];
    const int*   glab = (const int*)d_in[4];
    float* out = (float*)d_out;

    dim3 grid(NBX, NB);
    k_match<<<grid, 256>>>(preg, pcls, ancs, gbox, glab);
    k_select<<<NB, 1024>>>(out);
}

// round 9
// speedup vs baseline: 1.3097x; 1.3097x over previous
#include <cuda_runtime.h>
#include <math.h>

#define NB 64
#define NA 8732
#define NA4 2183            // NA/4 exact
#define NG 50
#define NC 21
#define NBX 18              // ceil(NA/512)
#define IOU_THR 0.5f
#define VXY 0.1f
#define VWH 0.2f
#define EPS16 9.765625e-4

// ---------------- device scratch ----------------
__device__ float    g_lossneg[NB * NA];
__device__ unsigned g_hist[NB * 2048];    // level-1 histogram (zero-init; re-zeroed by k_select)
__device__ float    g_psl1[NB * NBX];
__device__ float    g_pce [NB * NBX];
__device__ int      g_pnp [NB * NBX];
__device__ double   g_ob_cp[NB];
__device__ double   g_ob_cn[NB];
__device__ double   g_ob_np[NB];
__device__ double   g_ob_sl[NB];
__device__ int      g_ctr;

// ---------------- helpers ----------------
__device__ __forceinline__ double warpRedD(double v) {
    #pragma unroll
    for (int o = 16; o > 0; o >>= 1) v += __shfl_down_sync(0xFFFFFFFFu, v, o);
    return v;
}
__device__ __forceinline__ float warpRedF(float v) {
    #pragma unroll
    for (int o = 16; o > 0; o >>= 1) v += __shfl_down_sync(0xFFFFFFFFu, v, o);
    return v;
}
__device__ __forceinline__ float smoothL1(float d) {
    float ad = fabsf(d);
    return ad < 1.0f ? 0.5f * d * d : ad - 0.5f;
}
__device__ __forceinline__ unsigned ordkey(float f) {
    unsigned u = __float_as_uint(f);
    return u ^ ((u >> 31) ? 0xFFFFFFFFu : 0x80000000u);
}
__device__ __forceinline__ float ordval(unsigned k) {
    unsigned u = (k & 0x80000000u) ? (k ^ 0x80000000u) : ~k;
    return __uint_as_float(u);
}
__device__ __forceinline__ unsigned warpSufIncl(unsigned v, int lane) {
    #pragma unroll
    for (int d = 1; d < 32; d <<= 1) {
        unsigned t = __shfl_down_sync(0xFFFFFFFFu, v, d);
        if (lane + d < 32) v += t;
    }
    return v;
}

// ---------------- kernel 1: match + box loss + CE (2 anchors/thread) ----------------
__global__ __launch_bounds__(256) void k_match(const float* __restrict__ preg,
                        const float* __restrict__ pcls,
                        const float* __restrict__ ancs,
                        const float* __restrict__ gbox,
                        const int*   __restrict__ glab) {
    const int b = blockIdx.y;
    const int tid = threadIdx.x;
    const int a0 = blockIdx.x * 512 + tid;
    const int a1 = a0 + 256;

    __shared__ float4 s_gb[NG];
    __shared__ float  s_ga[NG];
    __shared__ int    s_gl[NG];
    if (tid < NG) {
        float4 gb = reinterpret_cast<const float4*>(gbox)[b * NG + tid];
        int    gl = glab[b * NG + tid];
        float  ag = (gb.z - gb.x) * (gb.w - gb.y);
        if (gl <= 0) { gb = make_float4(0.f, 0.f, 0.f, 0.f); ag = 0.f; }
        s_gb[tid] = gb;
        s_ga[tid] = ag;
        s_gl[tid] = gl;
    }
    __syncthreads();

    float sl1_c = 0.f, ce_c = 0.f;
    int pos_c = 0;

    const bool v0 = (a0 < NA), v1 = (a1 < NA);

    float4 anc0 = make_float4(0.5f, 0.5f, 1.f, 1.f), anc1 = anc0;
    if (v0) anc0 = reinterpret_cast<const float4*>(ancs)[a0];
    if (v1) anc1 = reinterpret_cast<const float4*>(ancs)[a1];

    float al0 = anc0.x - anc0.z * 0.5f, at0 = anc0.y - anc0.w * 0.5f;
    float ar0 = anc0.x + anc0.z * 0.5f, ab0 = anc0.y + anc0.w * 0.5f;
    float area0 = (ar0 - al0) * (ab0 - at0);
    float al1 = anc1.x - anc1.z * 0.5f, at1 = anc1.y - anc1.w * 0.5f;
    float ar1 = anc1.x + anc1.z * 0.5f, ab1 = anc1.y + anc1.w * 0.5f;
    float area1 = (ar1 - al1) * (ab1 - at1);

    float inb0 = -1.f, unb0 = 1.f, inb1 = -1.f, unb1 = 1.f;
    int bi0 = 0, bi1 = 0;
    #pragma unroll
    for (int g = 0; g < NG; g++) {
        float4 gb = s_gb[g];
        float ga = s_ga[g];
        {
            float ltx = fmaxf(gb.x, al0), lty = fmaxf(gb.y, at0);
            float rbx = fminf(gb.z, ar0), rby = fminf(gb.w, ab0);
            float w = fmaxf(rbx - ltx, 0.0f), h = fmaxf(rby - lty, 0.0f);
            float inter = w * h;
            float uni = ga + area0 - inter;
            if (inter * unb0 > inb0 * uni) { inb0 = inter; unb0 = uni; bi0 = g; }
        }
        {
            float ltx = fmaxf(gb.x, al1), lty = fmaxf(gb.y, at1);
            float rbx = fminf(gb.z, ar1), rby = fminf(gb.w, ab1);
            float w = fmaxf(rbx - ltx, 0.0f), h = fmaxf(rby - lty, 0.0f);
            float inter = w * h;
            float uni = ga + area1 - inter;
            if (inter * unb1 > inb1 * uni) { inb1 = inter; unb1 = uni; bi1 = g; }
        }
    }
    bool pos0 = (2.0f * inb0 >= unb0);
    bool pos1 = (2.0f * inb1 >= unb1);

    const float* pregb = preg + (size_t)b * 4 * NA;
    const float* pclsb = pcls + (size_t)b * NC * NA;
    unsigned* histb = &g_hist[b * 2048];

    if (v0) {
        float4 gb = s_gb[bi0];
        float gcx = (gb.x + gb.z) * 0.5f, gcy = (gb.y + gb.w) * 0.5f;
        float gw = gb.z - gb.x, gh = gb.w - gb.y;
        float tx = (gcx - anc0.x) / (anc0.z * VXY);
        float ty = (gcy - anc0.y) / (anc0.w * VXY);
        float tw = __logf(fmaxf(gw, 1e-6f) / anc0.z) * (1.0f / VWH);
        float th = __logf(fmaxf(gh, 1e-6f) / anc0.w) * (1.0f / VWH);
        float d0 = pregb[0 * NA + a0] - tx;
        float d1 = pregb[1 * NA + a0] - ty;
        float d2 = pregb[2 * NA + a0] - tw;
        float d3 = pregb[3 * NA + a0] - th;
        float sl1 = smoothL1(d0) + smoothL1(d1) + smoothL1(d2) + smoothL1(d3);

        const float* pc = pclsb + a0;
        float s = 0.0f;
        #pragma unroll
        for (int c = 0; c < NC; c++) s += __expf(pc[c * NA]);
        float lse = __logf(s);
        int lab = pos0 ? s_gl[bi0] : 0;
        float ce = lse - pc[lab * NA];

        g_lossneg[b * NA + a0] = pos0 ? -1.0f : ce;
        if (pos0) { pos_c++; ce_c += ce; sl1_c += sl1; }
        else atomicAdd(&histb[ordkey(ce) >> 21], 1u);
    }
    if (v1) {
        float4 gb = s_gb[bi1];
        float gcx = (gb.x + gb.z) * 0.5f, gcy = (gb.y + gb.w) * 0.5f;
        float gw = gb.z - gb.x, gh = gb.w - gb.y;
        float tx = (gcx - anc1.x) / (anc1.z * VXY);
        float ty = (gcy - anc1.y) / (anc1.w * VXY);
        float tw = __logf(fmaxf(gw, 1e-6f) / anc1.z) * (1.0f / VWH);
        float th = __logf(fmaxf(gh, 1e-6f) / anc1.w) * (1.0f / VWH);
        float d0 = pregb[0 * NA + a1] - tx;
        float d1 = pregb[1 * NA + a1] - ty;
        float d2 = pregb[2 * NA + a1] - tw;
        float d3 = pregb[3 * NA + a1] - th;
        float sl1 = smoothL1(d0) + smoothL1(d1) + smoothL1(d2) + smoothL1(d3);

        const float* pc = pclsb + a1;
        float s = 0.0f;
        #pragma unroll
        for (int c = 0; c < NC; c++) s += __expf(pc[c * NA]);
        float lse = __logf(s);
        int lab = pos1 ? s_gl[bi1] : 0;
        float ce = lse - pc[lab * NA];

        g_lossneg[b * NA + a1] = pos1 ? -1.0f : ce;
        if (pos1) { pos_c++; ce_c += ce; sl1_c += sl1; }
        else atomicAdd(&histb[ordkey(ce) >> 21], 1u);
    }

    sl1_c = warpRedF(sl1_c);
    ce_c  = warpRedF(ce_c);
    float posf = warpRedF((float)pos_c);
    __shared__ float sh0[8], sh1[8], sh2[8];
    int wid = tid >> 5, lid = tid & 31;
    if (lid == 0) { sh0[wid] = sl1_c; sh1[wid] = ce_c; sh2[wid] = posf; }
    __syncthreads();
    if (wid == 0) {
        float x0 = (lid < 8) ? sh0[lid] : 0.f;
        float x1 = (lid < 8) ? sh1[lid] : 0.f;
        float x2 = (lid < 8) ? sh2[lid] : 0.f;
        x0 = warpRedF(x0); x1 = warpRedF(x1); x2 = warpRedF(x2);
        if (lid == 0) {
            int p = b * NBX + blockIdx.x;
            g_psl1[p] = x0;
            g_pce [p] = x1;
            g_pnp [p] = (int)(x2 + 0.5f);
        }
    }
}

// select crossing bin among 2048 bins (4 per thread, 512 threads).
// h0..h3 = counts of bins 4*tid .. 4*tid+3. Writes *s_bin, *s_rem. Ends synced.
__device__ __forceinline__ void select4(unsigned h0, unsigned h1, unsigned h2, unsigned h3,
        unsigned K, unsigned* s_w, unsigned* s_w2,
        unsigned* s_bin, unsigned* s_rem, int tid, int lane, int wid) {
    unsigned c3 = h3, c2 = h2 + c3, c1 = h1 + c2, c0 = h0 + c1;  // within-thread suffixes
    unsigned v = warpSufIncl(c0, lane);
    if (lane == 0) s_w[wid] = v;
    __syncthreads();
    if (tid < 32) {
        unsigned t = (tid < 16) ? s_w[tid] : 0u;
        s_w2[tid] = warpSufIncl(t, tid);
    }
    __syncthreads();
    unsigned wexcl = (wid < 15) ? s_w2[wid + 1] : 0u;
    unsigned excl = v - c0 + wexcl;         // sum over bins strictly above my 4
    unsigned suf, abv;
    suf = excl + c0; abv = suf - h0; if (abv < K && K <= suf) { *s_bin = 4u * tid;     *s_rem = K - abv; }
    suf = excl + c1; abv = suf - h1; if (abv < K && K <= suf) { *s_bin = 4u * tid + 1; *s_rem = K - abv; }
    suf = excl + c2; abv = suf - h2; if (abv < K && K <= suf) { *s_bin = 4u * tid + 2; *s_rem = K - abv; }
    suf = excl + c3; abv = suf - h3; if (abv < K && K <= suf) { *s_bin = 4u * tid + 3; *s_rem = K - abv; }
    __syncthreads();
}

// ---------------- kernel 2: hierarchical exact top-K sum ----------------
// Level-1 histogram comes precomputed from k_match (negatives only; their keys
// have bit31 set so B1 >= 1024 and the -1.0 sentinels (bin 515) never match).
// Level-3 bins are exact 32-bit keys, so tie handling is exact.
__global__ __launch_bounds__(512) void k_select(float* __restrict__ out) {
    const int b = blockIdx.x;
    const int tid = threadIdx.x;
    const int lane = tid & 31;
    const int wid = tid >> 5;

    __shared__ unsigned s_h2[2048];
    __shared__ unsigned s_h3[2048];     // low 1024 used; upper half stays zero
    __shared__ float    s_sum3[1024];
    __shared__ unsigned s_w[16], s_w2[32];
    __shared__ unsigned s_bin, s_rem;
    __shared__ double s_np, s_ce, s_sl;
    __shared__ int s_ticket;
    __shared__ double sd[16];

    // load level-1 histogram (4 bins/thread) and re-zero it for the next replay
    uint4* gh4 = reinterpret_cast<uint4*>(&g_hist[b * 2048]);
    uint4 hh = gh4[tid];
    gh4[tid] = make_uint4(0, 0, 0, 0);

    // zero smem histograms
    s_h2[tid] = 0; s_h2[tid + 512] = 0; s_h2[tid + 1024] = 0; s_h2[tid + 1536] = 0;
    s_h3[tid] = 0; s_h3[tid + 512] = 0; s_h3[tid + 1024] = 0; s_h3[tid + 1536] = 0;
    s_sum3[tid] = 0.f; s_sum3[tid + 512] = 0.f;

    // warp 15 reduces per-block partials
    if (wid == 15) {
        double np = 0.0, ce = 0.0, sl = 0.0;
        if (lane < NBX) {
            int p = b * NBX + lane;
            np = (double)g_pnp[p];
            ce = (double)g_pce[p];
            sl = (double)g_psl1[p];
        }
        np = warpRedD(np); ce = warpRedD(ce); sl = warpRedD(sl);
        if (lane == 0) { s_np = np; s_ce = ce; s_sl = sl; }
    }
    __syncthreads();

    int npos = (int)(s_np + 0.5);
    int numneg = NA - npos;
    int K = (npos > 0) ? min(3 * npos, numneg) : (numneg > 0 ? 1 : 0);

    double dsum = 0.0;
    double negsum = 0.0;

    if (K > 0) {
        // ---- level 1: pick B1 from precomputed histogram ----
        select4(hh.x, hh.y, hh.z, hh.w, (unsigned)K, s_w, s_w2, &s_bin, &s_rem, tid, lane, wid);
        unsigned B1 = s_bin, rem1 = s_rem;
        __syncthreads();

        const float4* base4 = reinterpret_cast<const float4*>(&g_lossneg[b * NA]);

        // ---- pass 1: sum above B1, histogram bits[10,21) for bin==B1 ----
        for (int i = tid; i < NA4; i += 512) {
            float4 f = base4[i];
            {   unsigned k = ordkey(f.x), bn = k >> 21;
                if (bn > B1) dsum += (double)f.x;
                else if (bn == B1) atomicAdd(&s_h2[(k >> 10) & 2047u], 1u); }
            {   unsigned k = ordkey(f.y), bn = k >> 21;
                if (bn > B1) dsum += (double)f.y;
                else if (bn == B1) atomicAdd(&s_h2[(k >> 10) & 2047u], 1u); }
            {   unsigned k = ordkey(f.z), bn = k >> 21;
                if (bn > B1) dsum += (double)f.z;
                else if (bn == B1) atomicAdd(&s_h2[(k >> 10) & 2047u], 1u); }
            {   unsigned k = ordkey(f.w), bn = k >> 21;
                if (bn > B1) dsum += (double)f.w;
                else if (bn == B1) atomicAdd(&s_h2[(k >> 10) & 2047u], 1u); }
        }
        __syncthreads();

        // ---- level 2: pick B2 ----
        select4(s_h2[4 * tid], s_h2[4 * tid + 1], s_h2[4 * tid + 2], s_h2[4 * tid + 3],
                rem1, s_w, s_w2, &s_bin, &s_rem, tid, lane, wid);
        unsigned B2 = s_bin, rem2 = s_rem;
        __syncthreads();

        // ---- pass 2: within B1: sum above B2; exact-key histogram+sums for ==B2 ----
        for (int i = tid; i < NA4; i += 512) {
            float4 f = base4[i];
            {   unsigned k = ordkey(f.x);
                if ((k >> 21) == B1) { unsigned sb = (k >> 10) & 2047u;
                    if (sb > B2) dsum += (double)f.x;
                    else if (sb == B2) { atomicAdd(&s_h3[k & 1023u], 1u); atomicAdd(&s_sum3[k & 1023u], f.x); } } }
            {   unsigned k = ordkey(f.y);
                if ((k >> 21) == B1) { unsigned sb = (k >> 10) & 2047u;
                    if (sb > B2) dsum += (double)f.y;
                    else if (sb == B2) { atomicAdd(&s_h3[k & 1023u], 1u); atomicAdd(&s_sum3[k & 1023u], f.y); } } }
            {   unsigned k = ordkey(f.z);
                if ((k >> 21) == B1) { unsigned sb = (k >> 10) & 2047u;
                    if (sb > B2) dsum += (double)f.z;
                    else if (sb == B2) { atomicAdd(&s_h3[k & 1023u], 1u); atomicAdd(&s_sum3[k & 1023u], f.z); } } }
            {   unsigned k = ordkey(f.w);
                if ((k >> 21) == B1) { unsigned sb = (k >> 10) & 2047u;
                    if (sb > B2) dsum += (double)f.w;
                    else if (sb == B2) { atomicAdd(&s_h3[k & 1023u], 1u); atomicAdd(&s_sum3[k & 1023u], f.w); } } }
        }
        __syncthreads();

        // ---- level 3: pick B3 (bins are exact key values) ----
        select4(s_h3[4 * tid], s_h3[4 * tid + 1], s_h3[4 * tid + 2], s_h3[4 * tid + 3],
                rem2, s_w, s_w2, &s_bin, &s_rem, tid, lane, wid);
        unsigned B3 = s_bin, rem3 = s_rem;
        __syncthreads();

        // sum of exact-key bins above B3 (values within bin are identical -> fp32 exact-ish)
        float extra = 0.f;
        for (int j = tid; j < 1024; j += 512)
            if ((unsigned)j > B3) extra += s_sum3[j];
        dsum += (double)extra;

        unsigned pivot = (((B1 << 11) | B2) << 10) | B3;
        float pv = ordval(pivot);

        double s = warpRedD(dsum);
        if (lane == 0) sd[wid] = s;
        __syncthreads();
        if (wid == 0) {
            double t = (lane < 16) ? sd[lane] : 0.0;
            t = warpRedD(t);
            if (lane == 0) sd[0] = t + (double)rem3 * (double)pv;
        }
        __syncthreads();
        negsum = sd[0];
    }

    // publish per-batch results; last block combines
    if (tid == 0) {
        double nums = fmax(s_np, (double)EPS16);
        g_ob_cp[b] = s_ce / nums;
        g_ob_cn[b] = negsum / nums;
        g_ob_np[b] = s_np;
        g_ob_sl[b] = s_sl;
        __threadfence();
        s_ticket = atomicAdd(&g_ctr, 1);
    }
    __syncthreads();

    if (s_ticket == NB - 1) {
        double cp = 0.0, cn = 0.0, np = 0.0, sl = 0.0;
        if (tid < NB) {
            cp = g_ob_cp[tid]; cn = g_ob_cn[tid];
            np = g_ob_np[tid]; sl = g_ob_sl[tid];
        }
        cp = warpRedD(cp); cn = warpRedD(cn); np = warpRedD(np); sl = warpRedD(sl);
        __shared__ double f0[2], f1[2], f2[2], f3[2];
        if (lane == 0 && tid < NB) {
            f0[wid] = cp; f1[wid] = cn; f2[wid] = np; f3[wid] = sl;
        }
        __syncthreads();
        if (tid == 0) {
            double CP = f0[0] + f0[1];
            double CN = f1[0] + f1[1];
            double NP = f2[0] + f2[1];
            double SL = f3[0] + f3[1];
            double lbox = SL / fmax(NP, 1.0);
            out[0] = (float)(lbox + CP / (double)NB + CN / (double)NB);
            g_ctr = 0;
        }
    }
}

// ---------------- launch ----------------
extern "C" void kernel_launch(void* const* d_in, const int* in_sizes, int n_in,
                              void* d_out, int out_size) {
    const float* preg = (const float*)d_in[0];
    const float* pcls = (const float*)d_in[1];
    const float* ancs = (const float*)d_in[2];
    const float* gbox = (const float*)d_in[3];
    const int*   glab = (const int*)d_in[4];
    float* out = (float*)d_out;

    dim3 grid(NBX, NB);
    k_match<<<grid, 256>>>(preg, pcls, ancs, gbox, glab);
    k_select<<<NB, 512>>>(out);
}